// round 12
// baseline (speedup 1.0000x reference)
#include <cuda_runtime.h>
#include <cuda_fp16.h>

// Problem constants
#define B_DIM 8
#define C_DIM 64
#define T_DIM 128
#define N_DIM 207
#define TN    (T_DIM * N_DIM)
#define L2E   1.4426950408889634f

// Fused tiling
#define NS     16            // n per block (power of two: shift/mask indexing)
#define TT     16            // output t per block
#define PT     22            // TT + 6 halo
#define PIXKV  (PT * NS)     // 352 K/V pixel rows = 22 m16-tiles exactly
#define MTILES 22
#define STRH   70            // half stride of QKV smem rows [pix][o]
#define NTILES 13            // ceil(207/16)
#define NTHREADS 512

// Dynamic SMEM layout (bytes); total 194560 <= 227KB
#define SO_BIAS 0
#define SO_W    256                           // 64*72 halves = 9216
#define SO_AS   (SO_W + 64 * 72 * 2)          // 352*72 halves = 50688
#define SO_Q    (SO_AS + PIXKV * 72 * 2)      // 256*70 halves = 35840
#define SO_K    (SO_Q + TT * NS * STRH * 2)   // 352*70 halves = 49280
#define SO_V    (SO_K + PIXKV * STRH * 2)
#define SMEM_TOTAL (SO_V + PIXKV * STRH * 2)

__device__ __forceinline__ void mma_fp16(float* d, const unsigned* a, const unsigned* b) {
    asm volatile(
        "mma.sync.aligned.m16n8k16.row.col.f32.f16.f16.f32 "
        "{%0,%1,%2,%3},{%4,%5,%6,%7},{%8,%9},{%0,%1,%2,%3};\n"
        : "+f"(d[0]), "+f"(d[1]), "+f"(d[2]), "+f"(d[3])
        : "r"(a[0]), "r"(a[1]), "r"(a[2]), "r"(a[3]),
          "r"(b[0]), "r"(b[1]));
}

__device__ __forceinline__ float ex2f(float x) {
    float y;
    asm("ex2.approx.f32 %0, %1;" : "=f"(y) : "f"(x));
    return y;
}

// Proven stride-72 swizzle (R3..R10 proj): conflict-acceptable transposed
// 16-bit stores, conflict-free m16n8k16 A-fragment loads.
__device__ __forceinline__ int xs_idx(int j, int c) {
    return j * 72 + (c ^ (((j >> 3) & 3) << 1));
}

__global__ __launch_bounds__(NTHREADS, 1) void fused_kernel(
    float* __restrict__ out,
    const float* __restrict__ q, const float* __restrict__ k, const float* __restrict__ v,
    const float* __restrict__ Wq, const float* __restrict__ bq,
    const float* __restrict__ Wk, const float* __restrict__ bk,
    const float* __restrict__ Wv, const float* __restrict__ bv)
{
    extern __shared__ __align__(16) char sm[];
    float*  bias_s = (float*)(sm + SO_BIAS);
    __half* Wsm    = (__half*)(sm + SO_W);
    __half* As     = (__half*)(sm + SO_AS);
    __half* Qs     = (__half*)(sm + SO_Q);
    __half* Ks     = (__half*)(sm + SO_K);
    __half* Vs     = (__half*)(sm + SO_V);

    const int tid = threadIdx.x;
    const int n0  = blockIdx.x * NS;
    const int t0  = blockIdx.y * TT;
    const int b   = blockIdx.z;

    // Per-thread staging pixel (pix = tid for tid < PIXKV)  [verified R11]
    const int sp_t = tid >> 4;              // t_loc (NS=16)
    const int sp_n = tid & 15;
    const int sg_t = t0 - 3 + sp_t;
    const int sg_n = n0 + sp_n;
    const bool sp_ok = (tid < PIXKV) && (sg_t >= 0) && (sg_t < T_DIM) && (sg_n < N_DIM);
    const int tcl = (sg_t < 0) ? 0 : ((sg_t > 127) ? 127 : sg_t);
    const int ncl = (sg_n > 206) ? 206 : sg_n;
    const unsigned gbase = ((unsigned)(b * C_DIM) * T_DIM + (unsigned)tcl) * N_DIM + (unsigned)ncl;

    const int wid = tid >> 5, lane = tid & 31;
    const int lr = lane >> 2, lc = lane & 3;

    const float* Xz[3] = { q, k, v };
    const float* Wz[3] = { Wq, Wk, Wv };
    const float* bz[3] = { bq, bk, bv };

    #pragma unroll 1
    for (int z = 0; z < 3; z++) {
        const float* __restrict__ X = Xz[z];
        const float* __restrict__ W = Wz[z];

        __syncthreads();   // prior z consumers of Wsm/As/bias done

        // Stage W (fp16, stride 72: proven conflict-free B-frag reads)
        for (int i = tid; i < 64 * 64; i += NTHREADS) {
            int o = i >> 6, c = i & 63;
            Wsm[o * 72 + c] = __float2half_rn(W[i]);
        }
        if (tid < 64) bias_s[tid] = bz[z][tid];

        // Stage full transposed A tile [352 pix][64 c], one MLP-16 burst x4
        if (tid < PIXKV) {
            #pragma unroll 1
            for (int c0 = 0; c0 < 64; c0 += 16) {
                unsigned ga = gbase + (unsigned)c0 * TN;
                #pragma unroll
                for (int cl = 0; cl < 16; cl++) {
                    float x = sp_ok ? X[ga] : 0.0f;
                    As[xs_idx(tid, c0 + cl)] = __float2half_rn(x);
                    ga += TN;
                }
            }
        }
        __syncthreads();

        const float qs = (z == 0) ? L2E : 1.0f;
        __half* Dst = (z == 1) ? Ks : Vs;

        // Two o-halves: 32 accumulators/thread each
        #pragma unroll 1
        for (int oh = 0; oh < 2; oh++) {
            float acc[2][4][4] = {};

            #pragma unroll
            for (int kc = 0; kc < 4; kc++) {
                unsigned Bf[4][2];
                #pragma unroll
                for (int nt = 0; nt < 4; nt++) {
                    int o = oh * 32 + nt * 8 + lr;
                    int c = kc * 16 + 2 * lc;
                    Bf[nt][0] = *(const unsigned*)&Wsm[o * 72 + c];
                    Bf[nt][1] = *(const unsigned*)&Wsm[o * 72 + c + 8];
                }
                #pragma unroll
                for (int mt = 0; mt < 2; mt++) {
                    int tile = wid + 16 * mt;
                    if (tile < MTILES) {
                        int r0 = tile * 16 + lr, r1 = r0 + 8;
                        int c0 = kc * 16 + 2 * lc, c1 = c0 + 8;
                        unsigned Af[4];
                        Af[0] = *(const unsigned*)&As[xs_idx(r0, c0)];
                        Af[1] = *(const unsigned*)&As[xs_idx(r1, c0)];
                        Af[2] = *(const unsigned*)&As[xs_idx(r0, c1)];
                        Af[3] = *(const unsigned*)&As[xs_idx(r1, c1)];
                        #pragma unroll
                        for (int nt = 0; nt < 4; nt++)
                            mma_fp16(acc[mt][nt], Af, Bf[nt]);
                    }
                }
            }

            // Epilogue: rows are warp-private -> no sync needed. [logic verified R11]
            #pragma unroll
            for (int mt = 0; mt < 2; mt++) {
                int tile = wid + 16 * mt;
                if (tile >= MTILES) continue;
                #pragma unroll
                for (int nt = 0; nt < 4; nt++) {
                    int ob = oh * 32 + nt * 8 + 2 * lc;
                    float b0 = bias_s[ob], b1 = bias_s[ob + 1];
                    #pragma unroll
                    for (int h = 0; h < 2; h++) {
                        int row = tile * 16 + lr + h * 8;   // < 352 always
                        float y0 = (acc[mt][nt][2 * h + 0] + b0) * qs;
                        float y1 = (acc[mt][nt][2 * h + 1] + b1) * qs;
                        if (z == 0) {
                            // Q: keep t_loc in [3, 3+TT)
                            if (row >= 3 * NS && row < (3 + TT) * NS) {
                                *(__half2*)&Qs[(row - 3 * NS) * STRH + ob] =
                                    __floats2half2_rn(y0, y1);
                            }
                        } else {
                            // K/V: zero t-pad rows (reference pads AFTER projection)
                            bool kvz = (t0 == 0 && row < 3 * NS) ||
                                       (t0 == T_DIM - TT && row >= (3 + TT) * NS);
                            if (kvz) { y0 = 0.0f; y1 = 0.0f; }
                            *(__half2*)&Dst[row * STRH + ob] = __floats2half2_rn(y0, y1);
                        }
                    }
                }
            }
        }
    }

    __syncthreads();   // QKV smem fully built

    // ---- Attention: 7-tap sliding-window softmax from SMEM [logic verified R11] ----
    // 4096 items = 64 o x 4 t-groups x 16 n; item = 4 t-outputs sharing a
    // 10-row K/V window. 8 items per thread; shift/mask decomposition.
    #pragma unroll 1
    for (int it = 0; it < 8; it++) {
        int item  = tid + NTHREADS * it;
        int n_loc = item & 15;
        int rem   = item >> 4;      // 0..255
        int tg    = rem & 3;
        int o     = rem >> 2;       // 0..63
        int n     = n0 + n_loc;
        if (n >= N_DIM) continue;

        int base_pix = (tg * 4) * NS + n_loc;   // K/V row of t_out_local = tg*4, tap -3
        float kw[10], vw[10];
        #pragma unroll
        for (int r = 0; r < 10; r++) {
            int p = base_pix + r * NS;
            kw[r] = __half2float(Ks[p * STRH + o]);
            vw[r] = __half2float(Vs[p * STRH + o]);
        }

        unsigned obase = (((unsigned)b * C_DIM + (unsigned)o) * T_DIM +
                          (unsigned)(t0 + tg * 4)) * N_DIM + (unsigned)n;
        #pragma unroll
        for (int j = 0; j < 4; j++) {
            float qv = __half2float(Qs[(base_pix + j * NS) * STRH + o]);  // log2e-scaled
            float den = 0.0f, num = 0.0f;
            #pragma unroll
            for (int i = 0; i < 7; i++) {
                float e = ex2f(qv * kw[j + i]);   // pad rows: kw=0 -> e=1 (matches ref)
                den += e;
                num = fmaf(e, vw[j + i], num);
            }
            out[obase + (unsigned)(j * N_DIM)] = __fdividef(num, den);
        }
    }
}

// ---------------- launch ----------------
extern "C" void kernel_launch(void* const* d_in, const int* in_sizes, int n_in,
                              void* d_out, int out_size)
{
    (void)in_sizes; (void)n_in; (void)out_size;
    const float* q  = (const float*)d_in[0];
    const float* k  = (const float*)d_in[1];
    const float* v  = (const float*)d_in[2];
    const float* Wq = (const float*)d_in[3];
    const float* bq = (const float*)d_in[4];
    const float* Wk = (const float*)d_in[5];
    const float* bk = (const float*)d_in[6];
    const float* Wv = (const float*)d_in[7];
    const float* bv = (const float*)d_in[8];

    cudaFuncSetAttribute(fused_kernel,
                         cudaFuncAttributeMaxDynamicSharedMemorySize, SMEM_TOTAL);

    dim3 grid(NTILES, T_DIM / TT, B_DIM);
    fused_kernel<<<grid, NTHREADS, SMEM_TOTAL>>>(
        (float*)d_out, q, k, v, Wq, bq, Wk, bk, Wv, bv);
}

// round 14
// speedup vs baseline: 5.7793x; 5.7793x over previous
#include <cuda_runtime.h>
#include <cuda_fp16.h>

// Problem constants
#define B_DIM 8
#define C_DIM 64
#define T_DIM 128
#define N_DIM 207
#define TN    (T_DIM * N_DIM)   // 26496 valid pixels per (b, channel)
#define JT_BLK 96               // proj: pixels per block tile (26496 = 96*276)
#define NBLK_J (TN / JT_BLK)    // 276
#define L2E   1.4426950408889634f

// Padded scratch plane: [pad 624][valid 26496][pad 624] halves per (b,o).
// 624 = 3*207 rounded up to a multiple of 4 (keeps uint2 stores aligned);
// halo rows t=-3..-1 and t=128..130 live inside the pads and are zeroed.
#define TPLANE 27744
#define PADB   624
#define NPLANE (B_DIM * C_DIM)          // 512 planes per tensor

// fp16 scratch for projected Q (pre-scaled by log2e), K, V.
__device__ __align__(16) __half g_scr[3][(size_t)NPLANE * TPLANE];

// ---------------- helpers ----------------
// Swizzled half-index into the transposed X tile Xs[j][c] (see R3 notes):
// conflict-free for transposed 16-bit stores and m16n8k16 A-fragment loads.
__device__ __forceinline__ int xs_idx(int j, int c) {
    return j * 72 + (c ^ (((j >> 3) & 3) << 1));
}

__device__ __forceinline__ void mma_fp16(float* d, const unsigned* a, const unsigned* b) {
    asm volatile(
        "mma.sync.aligned.m16n8k16.row.col.f32.f16.f16.f32 "
        "{%0,%1,%2,%3},{%4,%5,%6,%7},{%8,%9},{%0,%1,%2,%3};\n"
        : "+f"(d[0]), "+f"(d[1]), "+f"(d[2]), "+f"(d[3])
        : "r"(a[0]), "r"(a[1]), "r"(a[2]), "r"(a[3]),
          "r"(b[0]), "r"(b[1]));
}

// Guaranteed single-MUFU exp2 (independent of fast-math flags)
__device__ __forceinline__ float ex2f(float x) {
    float y;
    asm("ex2.approx.f32 %0, %1;" : "=f"(y) : "f"(x));
    return y;
}

// ---------------- Kernel 0: zero the scratch halo pads ----------------
// 1536 planes (3 tensors x 512), 624 uints (front 312 + back 312) per plane.
__global__ __launch_bounds__(128) void zero_pads_kernel()
{
    unsigned* g = (unsigned*)g_scr;
    const unsigned p = blockIdx.x;                  // 0..1535
    const unsigned pb = p * (TPLANE / 2);           // uint base of plane
    for (int i = threadIdx.x; i < 624; i += 128) {
        unsigned off = (i < 312) ? (unsigned)i
                                 : (unsigned)((PADB + TN) / 2 + (i - 312));
        g[pb + off] = 0u;
    }
}

// ---------------- Kernel A: projections via fp16 tensor cores ----------------
// R7-proven structure; only change: padded-plane store base.
// grid = (276 j-tiles, 8 batches, 3 projections), 192 threads (6 warps).
#define YS_STRIDE 100   // fp32 words; conflict-free for fragment writes
__global__ __launch_bounds__(192) void proj_kernel(
    const float* __restrict__ q, const float* __restrict__ k, const float* __restrict__ v,
    const float* __restrict__ Wq, const float* __restrict__ bq,
    const float* __restrict__ Wk, const float* __restrict__ bk,
    const float* __restrict__ Wv, const float* __restrict__ bv)
{
    // Union: Xh (staging + MMA A operand, 13824 B) shares bytes with Ysm (25600 B)
    __shared__ __align__(16) char smem_u[64 * YS_STRIDE * sizeof(float)];
    __shared__ unsigned short Wh[64 * 72];
    __shared__ float bias_s[64];

    unsigned short* Xh = (unsigned short*)smem_u;
    float* Ysm = (float*)smem_u;

    const int z = blockIdx.z;
    const float* __restrict__ X = (z == 0) ? q : (z == 1) ? k : v;
    const float* __restrict__ W = (z == 0) ? Wq : (z == 1) ? Wk : Wv;
    const float* __restrict__ bb = (z == 0) ? bq : (z == 1) ? bk : bv;
    __half* __restrict__ O = g_scr[z];

    const int b   = blockIdx.y;
    const int j0  = blockIdx.x * JT_BLK;
    const int tid = threadIdx.x;

    // Weights -> fp16 SMEM (stride 72: B-fragment reads conflict-free)
    for (int idx = tid; idx < 64 * 64; idx += 192) {
        int o = idx >> 6, c = idx & 63;
        __half h = __float2half_rn(W[idx]);
        Wh[o * 72 + c] = *(unsigned short*)&h;
    }
    if (tid < 64) bias_s[tid] = bb[tid];

    // X tile [64 c][96 j] -> transposed fp16 Xs[j][c]
    {
        const int jl  = tid % JT_BLK;       // 0..95
        const int cst = tid / JT_BLK;       // 0 or 1
        const float* Xb = X + ((size_t)b * C_DIM) * TN + j0 + jl;
        #pragma unroll
        for (int c = 0; c < 64; c += 2) {
            int cc = c + cst;
            float x = Xb[(size_t)cc * TN];
            __half h = __float2half_rn(x);
            Xh[xs_idx(jl, cc)] = *(unsigned short*)&h;
        }
    }
    __syncthreads();

    // Warp tiling: 6 warps = 3 (j) x 2 (o); warp tile 32j x 32o
    const int wid = tid >> 5, lane = tid & 31;
    const int wj = wid % 3, wo = wid / 3;
    const int lr = lane >> 2, lc = lane & 3;

    const unsigned* Xh32 = (const unsigned*)Xh;
    const unsigned* Wh32 = (const unsigned*)Wh;

    float acc[2][4][4] = {};

    #pragma unroll
    for (int k0 = 0; k0 < 64; k0 += 16) {
        unsigned Ah[2][4];
        #pragma unroll
        for (int mt = 0; mt < 2; mt++) {
            int jb = wj * 32 + mt * 16;
            int r0 = jb + lr, r1 = jb + lr + 8;
            int c0 = k0 + 2 * lc, c1 = k0 + 2 * lc + 8;
            Ah[mt][0] = Xh32[xs_idx(r0, c0) >> 1];
            Ah[mt][1] = Xh32[xs_idx(r1, c0) >> 1];
            Ah[mt][2] = Xh32[xs_idx(r0, c1) >> 1];
            Ah[mt][3] = Xh32[xs_idx(r1, c1) >> 1];
        }
        unsigned Bh[4][2];
        #pragma unroll
        for (int nt = 0; nt < 4; nt++) {
            int o = wo * 32 + nt * 8 + lr;
            int c0 = k0 + 2 * lc;
            Bh[nt][0] = Wh32[(o * 72 + c0) >> 1];
            Bh[nt][1] = Wh32[(o * 72 + c0 + 8) >> 1];
        }
        #pragma unroll
        for (int mt = 0; mt < 2; mt++) {
            #pragma unroll
            for (int nt = 0; nt < 4; nt++) {
                mma_fp16(acc[mt][nt], Ah[mt], Bh[nt]);
            }
        }
    }

    // Epilogue: acc -> Ysm (f32, conflict-free) -> pack half2 -> coalesced STG.64
    __syncthreads();   // done reading Xh; safe to overwrite with Ysm
    const float qs = (z == 0) ? L2E : 1.0f;
    #pragma unroll
    for (int mt = 0; mt < 2; mt++) {
        #pragma unroll
        for (int nt = 0; nt < 4; nt++) {
            int jb = wj * 32 + mt * 16;
            int ob = wo * 32 + nt * 8 + 2 * lc;
            int r0 = jb + lr, r1 = r0 + 8;
            float b0 = bias_s[ob], b1 = bias_s[ob + 1];
            Ysm[ob * YS_STRIDE + r0]       = (acc[mt][nt][0] + b0) * qs;
            Ysm[(ob + 1) * YS_STRIDE + r0] = (acc[mt][nt][1] + b1) * qs;
            Ysm[ob * YS_STRIDE + r1]       = (acc[mt][nt][2] + b0) * qs;
            Ysm[(ob + 1) * YS_STRIDE + r1] = (acc[mt][nt][3] + b1) * qs;
        }
    }
    __syncthreads();

    {
        // Padded-plane base: (b*64+o)*TPLANE + PADB + j0 (all terms = 0 mod 4)
        if (lane < 24) {
            #pragma unroll
            for (int o = wid; o < 64; o += 6) {   // 6 warps cover 64 rows
                float4 val = *(const float4*)&Ysm[o * YS_STRIDE + 4 * lane];
                __half2 h01 = __floats2half2_rn(val.x, val.y);
                __half2 h23 = __floats2half2_rn(val.z, val.w);
                uint2 pk;
                pk.x = *(unsigned*)&h01;
                pk.y = *(unsigned*)&h23;
                size_t ob = (size_t)(b * C_DIM + o) * TPLANE + PADB + j0 + 4 * lane;
                *(uint2*)&O[ob] = pk;   // 8B aligned
            }
        }
    }
}

// ---------------- Kernel B: 7-tap sliding-window softmax, guard-free ----------------
// grid = (4 t-chunks of 32, 64 channels, 8 batches), 224 threads (lane = n).
// Padded scratch: t in [-3, 130] always addressable, halo rows are true zeros
// -> NO boundary selects/clamps anywhere. No max-sub (|score*log2e| << 126;
// zero halo rows give exp2(0)=1 matching the reference softmax exactly).
#define TTC 32
__global__ __launch_bounds__(224) void attn_kernel(float* __restrict__ out)
{
    const int n = threadIdx.x;
    if (n >= N_DIM) return;

    const int t0 = blockIdx.x * TTC;
    const int o  = blockIdx.y;
    const int b  = blockIdx.z;
    const unsigned base = (unsigned)(b * C_DIM + o) * TPLANE + PADB;

    const __half* __restrict__ Q = g_scr[0];
    const __half* __restrict__ K = g_scr[1];
    const __half* __restrict__ V = g_scr[2];

    float kw[7], vw[7];
    {
        unsigned g = base + (unsigned)(t0 - 3) * N_DIM + n;   // always valid (pads)
        #pragma unroll
        for (int i = 0; i < 6; i++) {
            kw[i] = __half2float(K[g]);
            vw[i] = __half2float(V[g]);
            g += N_DIM;
        }
    }

    unsigned gi = base + (unsigned)t0 * N_DIM + n;   // scratch index of (t, n)
    unsigned go = ((unsigned)(b * C_DIM + o) * T_DIM + (unsigned)t0) * N_DIM + n;
    #pragma unroll 4
    for (int tl = 0; tl < TTC; tl++) {
        unsigned gl = gi + 3 * N_DIM;                // t+3, valid via pad
        kw[6] = __half2float(K[gl]);
        vw[6] = __half2float(V[gl]);

        float qv = __half2float(Q[gi]);              // already log2e-scaled

        float den = 0.0f, num = 0.0f;
        #pragma unroll
        for (int i = 0; i < 7; i++) {
            float e = ex2f(qv * kw[i]);
            den += e;
            num = fmaf(e, vw[i], num);
        }
        out[go] = __fdividef(num, den);

        #pragma unroll
        for (int i = 0; i < 6; i++) { kw[i] = kw[i + 1]; vw[i] = vw[i + 1]; }
        gi += N_DIM;
        go += N_DIM;
    }
}

// ---------------- launch ----------------
extern "C" void kernel_launch(void* const* d_in, const int* in_sizes, int n_in,
                              void* d_out, int out_size)
{
    (void)in_sizes; (void)n_in; (void)out_size;
    const float* q  = (const float*)d_in[0];
    const float* k  = (const float*)d_in[1];
    const float* v  = (const float*)d_in[2];
    const float* Wq = (const float*)d_in[3];
    const float* bq = (const float*)d_in[4];
    const float* Wk = (const float*)d_in[5];
    const float* bk = (const float*)d_in[6];
    const float* Wv = (const float*)d_in[7];
    const float* bv = (const float*)d_in[8];

    zero_pads_kernel<<<3 * NPLANE, 128>>>();

    dim3 gA(NBLK_J, B_DIM, 3);
    proj_kernel<<<gA, 192>>>(q, k, v, Wq, bq, Wk, bk, Wv, bv);

    dim3 gB(T_DIM / TTC, C_DIM, B_DIM);
    attn_kernel<<<gB, 224>>>((float*)d_out);
}